// round 13
// baseline (speedup 1.0000x reference)
#include <cuda_runtime.h>
#include <cuda_fp16.h>
#include <cstdint>

// Problem constants
#define B_   4
#define T_   4096
#define C_   1024
#define HD   64
#define M_   (B_ * T_)      // 16384 rows
#define NW   192            // q(64) | k(64) | v(64) fused cols
#define WIN  128            // ALiBi window (exact to ~e^-89)

// Scratch: fused qkv fp16 [M_][192]
__device__ __align__(16) __half g_h[(size_t)M_ * NW];
__device__ __align__(16) char g_wBh[16 * 24576];  // W fp16, per-chunk SW128 images

// ---------------- smem / mma helpers ----------------
__device__ __forceinline__ uint32_t smem_u32(const void* p) {
    uint32_t a;
    asm("{ .reg .u64 t; cvta.to.shared.u64 t, %1; cvt.u32.u64 %0, t; }"
        : "=r"(a) : "l"(p));
    return a;
}
#define SW128(off) ((off) ^ (((off) >> 3) & 0x70))

__device__ __forceinline__ void ldsm_x4(uint32_t* r, uint32_t addr) {
    asm volatile("ldmatrix.sync.aligned.m8n8.x4.shared.b16 {%0,%1,%2,%3}, [%4];"
                 : "=r"(r[0]), "=r"(r[1]), "=r"(r[2]), "=r"(r[3]) : "r"(addr));
}
__device__ __forceinline__ void ldsm_x4t(uint32_t* r, uint32_t addr) {
    asm volatile("ldmatrix.sync.aligned.m8n8.x4.trans.shared.b16 {%0,%1,%2,%3}, [%4];"
                 : "=r"(r[0]), "=r"(r[1]), "=r"(r[2]), "=r"(r[3]) : "r"(addr));
}
__device__ __forceinline__ void mma16816h(float* c, const uint32_t* a,
                                          const uint32_t* b) {
    asm volatile(
        "mma.sync.aligned.m16n8k16.row.col.f32.f16.f16.f32 "
        "{%0,%1,%2,%3}, {%4,%5,%6,%7}, {%8,%9}, {%0,%1,%2,%3};"
        : "+f"(c[0]), "+f"(c[1]), "+f"(c[2]), "+f"(c[3])
        : "r"(a[0]), "r"(a[1]), "r"(a[2]), "r"(a[3]), "r"(b[0]), "r"(b[1]));
}
__device__ __forceinline__ void cp_async16(uint32_t s, const void* g) {
    asm volatile("{ .reg .u64 gp; cvta.to.global.u64 gp, %1;"
                 " cp.async.cg.shared.global [%0], [gp], 16; }"
                 :: "r"(s), "l"(g) : "memory");
}
__device__ __forceinline__ uint32_t h2pack(float hi_f, float lo_f) {
    uint32_t r;   // r[15:0] = fp16(lo_f), r[31:16] = fp16(hi_f)
    asm("cvt.rn.f16x2.f32 %0, %1, %2;" : "=r"(r) : "f"(hi_f), "f"(lo_f));
    return r;
}
__device__ __forceinline__ float ex2(float x) {
    float r;
    asm("ex2.approx.ftz.f32 %0, %1;" : "=f"(r) : "f"(x));
    return r;
}

// ---------------------------------------------------------------------------
// Prep kernel: round W to fp16, per-chunk SW128 images.
// ---------------------------------------------------------------------------
__global__ __launch_bounds__(256) void prep_w(const float* __restrict__ wq,
                                              const float* __restrict__ wk,
                                              const float* __restrict__ wv) {
    int idx = blockIdx.x * 256 + threadIdx.x;   // 0..24575
    int n = idx >> 7;
    int k = (idx & 127) * 8;
    const float* wr = (n < 64)  ? (wq + (size_t)n * C_)
                    : (n < 128) ? (wk + (size_t)(n - 64) * C_)
                                : (wv + (size_t)(n - 128) * C_);
    float4 v0 = *(const float4*)(wr + k);
    float4 v1 = *(const float4*)(wr + k + 4);
    int ch = k >> 6, koff = k & 63;
    uint4 p;
    p.x = h2pack(v0.y, v0.x);
    p.y = h2pack(v0.w, v0.z);
    p.z = h2pack(v1.y, v1.x);
    p.w = h2pack(v1.w, v1.z);
    *(uint4*)(g_wBh + ch * 24576 + SW128((uint32_t)(n * 128 + koff * 2))) = p;
}

// ---------------------------------------------------------------------------
// Kernel 1: QKV projection via mma.sync fp16 (single-term W).
// BM=64, BN=192, BK=64, 256 threads, 8 warps = 2(M) x 4(N), warp tile 32x48.
// Double-buffered smem (32KB/buf): A fp16 @0 (8KB), Bh @8192 (24KB).
// Distance-2 x prefetch: LDG for chunk ch+2 issue at top of chunk ch,
// converted at end of chunk ch+1 -> DRAM latency fully covered.
// ---------------------------------------------------------------------------
#define QK_BUF 32768
#define QK_SMEM (2 * QK_BUF)

__global__ __launch_bounds__(256) void qkv_mma_kernel(const float* __restrict__ x) {
    extern __shared__ char sm[];
    const uint32_t sb = smem_u32(sm);
    const int tid = threadIdx.x;
    const int wid = tid >> 5;
    const int lane = tid & 31;
    const int rowBase = blockIdx.x * 64;

    const int wm = (wid >> 2) * 32;
    const int wn = (wid & 3) * 48;

    float acc[2][6][4];
#pragma unroll
    for (int i = 0; i < 2; i++)
#pragma unroll
        for (int j = 0; j < 6; j++)
#pragma unroll
            for (int k = 0; k < 4; k++) acc[i][j][k] = 0.0f;

    const uint32_t a_row = (uint32_t)(lane & 15);
    const uint32_t a_kb  = (uint32_t)((lane >> 4) * 16);
    const uint32_t b_n   = (uint32_t)((lane & 7) + ((lane >> 4) << 3));
    const uint32_t b_kb  = (uint32_t)(((lane >> 3) & 1) * 16);

    const int ar0 = tid >> 3;          // rows ar0, ar0+32
    const int ac8 = tid & 7;

    // x prefetch slots: av[s] holds chunk with (ch & 1) == s
    float4 av[2][4];

    // load chunk `c` of x into slot `s`
    auto ldx = [&](int c, int s) {
        const int k0 = c * 64;
#pragma unroll
        for (int t = 0; t < 2; t++) {
            const float* src = x + (size_t)(rowBase + ar0 + t * 32) * C_ + k0 + ac8 * 8;
            av[s][2 * t] = *(const float4*)src;
            av[s][2 * t + 1] = *(const float4*)(src + 4);
        }
    };
    // convert slot `s` into buffer base `bb`
    auto cvtA = [&](int s, uint32_t bb) {
#pragma unroll
        for (int t = 0; t < 2; t++) {
            uint4 p;
            p.x = h2pack(av[s][2 * t].y, av[s][2 * t].x);
            p.y = h2pack(av[s][2 * t].w, av[s][2 * t].z);
            p.z = h2pack(av[s][2 * t + 1].y, av[s][2 * t + 1].x);
            p.w = h2pack(av[s][2 * t + 1].w, av[s][2 * t + 1].z);
            uint32_t off = (uint32_t)((ar0 + t * 32) * 128 + ac8 * 16);
            *(uint4*)(sm + bb + SW128(off)) = p;
        }
    };

    // ---- prologue ----
    {
#pragma unroll
        for (int t = 0; t < 6; t++)
            cp_async16(sb + 8192 + tid * 16 + t * 4096, g_wBh + tid * 16 + t * 4096);
        asm volatile("cp.async.commit_group;" ::: "memory");
        ldx(0, 0);
        ldx(1, 1);
        cvtA(0, 0);
        asm volatile("cp.async.wait_group 0;" ::: "memory");
        __syncthreads();
    }

    for (int ch = 0; ch < 16; ch++) {
        const uint32_t cb = (uint32_t)(ch & 1) * QK_BUF;
        const uint32_t nb = (uint32_t)((ch + 1) & 1) * QK_BUF;
        const bool more = (ch < 15);

        // distance-2 x prefetch into the slot just freed (chunk ch's slot)
        if (ch + 2 < 16) ldx(ch + 2, ch & 1);

        if (more) {
            const char* gh = g_wBh + (ch + 1) * 24576;
#pragma unroll
            for (int t = 0; t < 6; t++)
                cp_async16(sb + nb + 8192 + tid * 16 + t * 4096, gh + tid * 16 + t * 4096);
            asm volatile("cp.async.commit_group;" ::: "memory");
        }

#pragma unroll
        for (int s = 0; s < 4; s++) {
            const uint32_t ks16 = (uint32_t)(s * 32);
            uint32_t bh[3][4];
#pragma unroll
            for (int tn = 0; tn < 3; tn++) {
                uint32_t off = (uint32_t)((wn + tn * 16 + b_n) * 128) + ks16 + b_kb;
                ldsm_x4(bh[tn], sb + cb + 8192 + SW128(off));
            }
            uint32_t af[2][4];
#pragma unroll
            for (int tm = 0; tm < 2; tm++) {
                uint32_t off = (uint32_t)((wm + tm * 16 + a_row) * 128) + ks16 + a_kb;
                ldsm_x4(af[tm], sb + cb + SW128(off));
            }
#pragma unroll
            for (int tm = 0; tm < 2; tm++)
#pragma unroll
                for (int tn = 0; tn < 3; tn++) {
                    mma16816h(acc[tm][tn * 2 + 0], af[tm], &bh[tn][0]);
                    mma16816h(acc[tm][tn * 2 + 1], af[tm], &bh[tn][2]);
                }
        }

        if (more) {
            cvtA((ch + 1) & 1, nb);     // chunk ch+1's x, loaded one chunk ago
            asm volatile("cp.async.wait_group 0;" ::: "memory");
        }
        __syncthreads();
    }

    // Epilogue: store fp16 plane
    const int er = lane >> 2;
    const int ec = (lane & 3) * 2;
#pragma unroll
    for (int tm = 0; tm < 2; tm++) {
        int r0 = rowBase + wm + tm * 16 + er;
#pragma unroll
        for (int tn = 0; tn < 6; tn++) {
            int cc = wn + tn * 8 + ec;
            *(uint32_t*)(g_h + (size_t)r0 * NW + cc) =
                h2pack(acc[tm][tn][1], acc[tm][tn][0]);
            *(uint32_t*)(g_h + (size_t)(r0 + 8) * NW + cc) =
                h2pack(acc[tm][tn][3], acc[tm][tn][2]);
        }
    }
}

// ---------------------------------------------------------------------------
// Kernel 2: banded tensor-core attention, 1-term fp16 PV (unchanged).
// ---------------------------------------------------------------------------
#define ATT_Q  0
#define ATT_K  8192
#define ATT_VH 32768
#define ATT_SMEM 57344
#define C1f 0.045084246f      // (1/32) * log2(e)
#define C2f 1.0201941f        // slope * log2(e)

__global__ __launch_bounds__(128) void attn_kernel(float* __restrict__ out) {
    extern __shared__ char sm[];
    const uint32_t sb = smem_u32(sm);
    const int b = blockIdx.y;
    const int q0 = blockIdx.x * 64;
    const int tid = threadIdx.x;
    const int w = tid >> 5;
    const int lane = tid & 31;

#pragma unroll
    for (int t = 0; t < 16; t++) {
        int idx = tid + t * 128;
        const __half* src;
        uint32_t dst;
        if (idx < 512) {
            int qr = idx >> 3, c = idx & 7;
            src = g_h + (size_t)(b * T_ + q0 + qr) * NW + c * 8;
            dst = sb + ATT_Q + SW128((uint32_t)(qr * 128 + c * 16));
        } else {
            int i2 = idx - 512;
            int r = i2 >> 3, c = i2 & 7;
            int j = q0 - 128 + r;
            if (j < 0) j = 0;
            src = g_h + (size_t)(b * T_ + j) * NW + 64 + c * 8;
            dst = sb + ATT_K + SW128((uint32_t)(r * 128 + c * 16));
        }
        cp_async16(dst, src);
    }
    asm volatile("cp.async.commit_group;" ::: "memory");
#pragma unroll
    for (int t = 0; t < 12; t++) {
        int idx = tid + t * 128;
        int r = idx >> 3, c = idx & 7;
        int j = q0 - 128 + r;
        if (j < 0) j = 0;
        const __half* src = g_h + (size_t)(b * T_ + j) * NW + 128 + c * 8;
        uint32_t dst = sb + ATT_VH + SW128((uint32_t)(r * 128 + c * 16));
        cp_async16(dst, src);
    }
    asm volatile("cp.async.commit_group;" ::: "memory");
    asm volatile("cp.async.wait_group 1;" ::: "memory");
    __syncthreads();

    const uint32_t a_row = (uint32_t)(lane & 15);
    const uint32_t a_kb  = (uint32_t)((lane >> 4) * 16);
    const uint32_t b_n   = (uint32_t)((lane & 7) + ((lane >> 4) << 3));
    const uint32_t b_kb  = (uint32_t)(((lane >> 3) & 1) * 16);

    uint32_t af[4][4];
#pragma unroll
    for (int s = 0; s < 4; s++)
        ldsm_x4(af[s], sb + ATT_Q +
                SW128((uint32_t)((w * 16 + a_row) * 128 + s * 32) + a_kb));

    float c[18][4];
#pragma unroll
    for (int j = 0; j < 18; j++)
#pragma unroll
        for (int k = 0; k < 4; k++) c[j][k] = 0.0f;

#pragma unroll
    for (int G = 0; G < 9; G++) {
        const int grow = (w + G) * 16;
#pragma unroll
        for (int s = 0; s < 4; s++) {
            uint32_t bk[4];
            ldsm_x4(bk, sb + ATT_K +
                    SW128((uint32_t)((grow + b_n) * 128 + s * 32) + b_kb));
            mma16816h(c[2 * G], af[s], &bk[0]);
            mma16816h(c[2 * G + 1], af[s], &bk[2]);
        }
    }

    const int g = lane >> 2;
    const int tc2 = (lane & 3) * 2;
    float rs0 = 0.0f, rs1 = 0.0f;
#pragma unroll
    for (int jt = 0; jt < 18; jt++) {
        int nb = 16 * w + 8 * jt + tc2;
        int j0 = q0 - 128 + nb;
        int d0 = g + 128 - 8 * jt - tc2;
        int d1 = d0 - 1, d2 = d0 + 8, d3 = d0 + 7;
        float p0 = ex2(fmaf(c[jt][0], C1f, -(float)d0 * C2f));
        float p1 = ex2(fmaf(c[jt][1], C1f, -(float)d1 * C2f));
        float p2 = ex2(fmaf(c[jt][2], C1f, -(float)d2 * C2f));
        float p3 = ex2(fmaf(c[jt][3], C1f, -(float)d3 * C2f));
        p0 = (d0 >= 0 && d0 < WIN && j0 >= 0) ? p0 : 0.0f;
        p1 = (d1 >= 0 && d1 < WIN && j0 + 1 >= 0) ? p1 : 0.0f;
        p2 = (d2 >= 0 && d2 < WIN && j0 >= 0) ? p2 : 0.0f;
        p3 = (d3 >= 0 && d3 < WIN && j0 + 1 >= 0) ? p3 : 0.0f;
        c[jt][0] = p0; c[jt][1] = p1; c[jt][2] = p2; c[jt][3] = p3;
        rs0 += p0 + p1;
        rs1 += p2 + p3;
    }
    rs0 += __shfl_xor_sync(0xffffffffu, rs0, 1);
    rs1 += __shfl_xor_sync(0xffffffffu, rs1, 1);
    rs0 += __shfl_xor_sync(0xffffffffu, rs0, 2);
    rs1 += __shfl_xor_sync(0xffffffffu, rs1, 2);
    const float rinv0 = 1.0f / rs0;
    const float rinv1 = 1.0f / rs1;

    asm volatile("cp.async.wait_group 0;" ::: "memory");
    __syncthreads();

    float o[8][4];
#pragma unroll
    for (int j = 0; j < 8; j++)
#pragma unroll
        for (int k = 0; k < 4; k++) o[j][k] = 0.0f;

    const uint32_t vrow = (uint32_t)((lane & 7) + 8 * ((lane >> 3) & 1));
    const uint32_t vcb  = (uint32_t)(16 * (lane >> 4));

#pragma unroll
    for (int ss = 0; ss < 9; ss++) {
        const int s = w + ss;
        uint32_t aph[4];
        aph[0] = h2pack(c[2 * ss][1], c[2 * ss][0]);
        aph[1] = h2pack(c[2 * ss][3], c[2 * ss][2]);
        aph[2] = h2pack(c[2 * ss + 1][1], c[2 * ss + 1][0]);
        aph[3] = h2pack(c[2 * ss + 1][3], c[2 * ss + 1][2]);
#pragma unroll
        for (int H = 0; H < 4; H++) {
            uint32_t ro = SW128((uint32_t)((16 * s + vrow) * 128 + 32 * H) + vcb);
            uint32_t vh[4];
            ldsm_x4t(vh, sb + ATT_VH + ro);
            mma16816h(o[2 * H], aph, &vh[0]);
            mma16816h(o[2 * H + 1], aph, &vh[2]);
        }
    }

    const int r0 = b * T_ + q0 + 16 * w + g;
#pragma unroll
    for (int j = 0; j < 8; j++) {
        *(float2*)(out + (size_t)r0 * HD + 8 * j + tc2) =
            make_float2(o[j][0] * rinv0, o[j][1] * rinv0);
        *(float2*)(out + (size_t)(r0 + 8) * HD + 8 * j + tc2) =
            make_float2(o[j][2] * rinv1, o[j][3] * rinv1);
    }
}

// ---------------------------------------------------------------------------
extern "C" void kernel_launch(void* const* d_in, const int* in_sizes, int n_in,
                              void* d_out, int out_size) {
    const float* x  = (const float*)d_in[0];
    const float* wq = (const float*)d_in[1];
    const float* wk = (const float*)d_in[2];
    const float* wv = (const float*)d_in[3];
    float* out = (float*)d_out;

    prep_w<<<96, 256>>>(wq, wk, wv);
    cudaFuncSetAttribute(qkv_mma_kernel,
                         cudaFuncAttributeMaxDynamicSharedMemorySize, QK_SMEM);
    qkv_mma_kernel<<<M_ / 64, 256, QK_SMEM>>>(x);
    cudaFuncSetAttribute(attn_kernel,
                         cudaFuncAttributeMaxDynamicSharedMemorySize, ATT_SMEM);
    attn_kernel<<<dim3(T_ / 64, B_), 128, ATT_SMEM>>>(out);
}

// round 14
// speedup vs baseline: 1.2264x; 1.2264x over previous
#include <cuda_runtime.h>
#include <cuda_fp16.h>
#include <cstdint>

// Problem constants
#define B_   4
#define T_   4096
#define C_   1024
#define HD   64
#define M_   (B_ * T_)      // 16384 rows
#define NW   192            // q(64) | k(64) | v(64) fused cols
#define WIN  128            // ALiBi window (exact to ~e^-89)

// Scratch: fused qkv fp16 [M_][192]
__device__ __align__(16) __half g_h[(size_t)M_ * NW];
__device__ __align__(16) char g_wBh[16 * 24576];  // W fp16, per-chunk SW128 images

// ---------------- smem / mma helpers ----------------
__device__ __forceinline__ uint32_t smem_u32(const void* p) {
    uint32_t a;
    asm("{ .reg .u64 t; cvta.to.shared.u64 t, %1; cvt.u32.u64 %0, t; }"
        : "=r"(a) : "l"(p));
    return a;
}
#define SW128(off) ((off) ^ (((off) >> 3) & 0x70))

__device__ __forceinline__ void ldsm_x4(uint32_t* r, uint32_t addr) {
    asm volatile("ldmatrix.sync.aligned.m8n8.x4.shared.b16 {%0,%1,%2,%3}, [%4];"
                 : "=r"(r[0]), "=r"(r[1]), "=r"(r[2]), "=r"(r[3]) : "r"(addr));
}
__device__ __forceinline__ void ldsm_x4t(uint32_t* r, uint32_t addr) {
    asm volatile("ldmatrix.sync.aligned.m8n8.x4.trans.shared.b16 {%0,%1,%2,%3}, [%4];"
                 : "=r"(r[0]), "=r"(r[1]), "=r"(r[2]), "=r"(r[3]) : "r"(addr));
}
__device__ __forceinline__ void mma16816h(float* c, const uint32_t* a,
                                          const uint32_t* b) {
    asm volatile(
        "mma.sync.aligned.m16n8k16.row.col.f32.f16.f16.f32 "
        "{%0,%1,%2,%3}, {%4,%5,%6,%7}, {%8,%9}, {%0,%1,%2,%3};"
        : "+f"(c[0]), "+f"(c[1]), "+f"(c[2]), "+f"(c[3])
        : "r"(a[0]), "r"(a[1]), "r"(a[2]), "r"(a[3]), "r"(b[0]), "r"(b[1]));
}
__device__ __forceinline__ void cp_async16(uint32_t s, const void* g) {
    asm volatile("{ .reg .u64 gp; cvta.to.global.u64 gp, %1;"
                 " cp.async.cg.shared.global [%0], [gp], 16; }"
                 :: "r"(s), "l"(g) : "memory");
}
__device__ __forceinline__ uint32_t h2pack(float hi_f, float lo_f) {
    uint32_t r;   // r[15:0] = fp16(lo_f), r[31:16] = fp16(hi_f)
    asm("cvt.rn.f16x2.f32 %0, %1, %2;" : "=r"(r) : "f"(hi_f), "f"(lo_f));
    return r;
}
__device__ __forceinline__ float ex2(float x) {
    float r;
    asm("ex2.approx.ftz.f32 %0, %1;" : "=f"(r) : "f"(x));
    return r;
}

// ---------------------------------------------------------------------------
// Prep kernel: round W to fp16, per-chunk SW128 images.
// ---------------------------------------------------------------------------
__global__ __launch_bounds__(256) void prep_w(const float* __restrict__ wq,
                                              const float* __restrict__ wk,
                                              const float* __restrict__ wv) {
    int idx = blockIdx.x * 256 + threadIdx.x;   // 0..24575
    int n = idx >> 7;
    int k = (idx & 127) * 8;
    const float* wr = (n < 64)  ? (wq + (size_t)n * C_)
                    : (n < 128) ? (wk + (size_t)(n - 64) * C_)
                                : (wv + (size_t)(n - 128) * C_);
    float4 v0 = *(const float4*)(wr + k);
    float4 v1 = *(const float4*)(wr + k + 4);
    int ch = k >> 6, koff = k & 63;
    uint4 p;
    p.x = h2pack(v0.y, v0.x);
    p.y = h2pack(v0.w, v0.z);
    p.z = h2pack(v1.y, v1.x);
    p.w = h2pack(v1.w, v1.z);
    *(uint4*)(g_wBh + ch * 24576 + SW128((uint32_t)(n * 128 + koff * 2))) = p;
}

// ---------------------------------------------------------------------------
// Kernel 1: QKV projection via mma.sync fp16 (single-term W).
// BM=64, BN=192, BK=64, 256 threads, 8 warps = 2(M) x 4(N), warp tile 32x48.
// Per-buffer smem (48KB): A fp16 @0 (8KB), Bh @8192 (24KB), Xstage @32768
// (16KB fp32). Distance-2 x prefetch via cp.async into Xstage (zero register
// cost). Two commit groups per chunk; wait_group 1 keeps X(ch+2) in flight.
// ---------------------------------------------------------------------------
#define QK_XS 32768
#define QK_BUF 49152
#define QK_SMEM (2 * QK_BUF)

__global__ __launch_bounds__(256) void qkv_mma_kernel(const float* __restrict__ x) {
    extern __shared__ char sm[];
    const uint32_t sb = smem_u32(sm);
    const int tid = threadIdx.x;
    const int wid = tid >> 5;
    const int lane = tid & 31;
    const int rowBase = blockIdx.x * 64;

    const int wm = (wid >> 2) * 32;
    const int wn = (wid & 3) * 48;

    float acc[2][6][4];
#pragma unroll
    for (int i = 0; i < 2; i++)
#pragma unroll
        for (int j = 0; j < 6; j++)
#pragma unroll
            for (int k = 0; k < 4; k++) acc[i][j][k] = 0.0f;

    const uint32_t a_row = (uint32_t)(lane & 15);
    const uint32_t a_kb  = (uint32_t)((lane >> 4) * 16);
    const uint32_t b_n   = (uint32_t)((lane & 7) + ((lane >> 4) << 3));
    const uint32_t b_kb  = (uint32_t)(((lane >> 3) & 1) * 16);

    const int ar0 = tid >> 3;          // rows ar0, ar0+32
    const int ac8 = tid & 7;
    // this thread's staging region: rows {ar0, ar0+32}, floats [ac8*8, ac8*8+8)
    const uint32_t st0 = (uint32_t)(ar0 * 256 + ac8 * 32);        // byte offsets
    const uint32_t st1 = (uint32_t)((ar0 + 32) * 256 + ac8 * 32);

    // issue X-chunk c cp.asyncs into buffer base bb's stage
    auto issueX = [&](int c, uint32_t bb) {
        const int k0 = c * 64;
        const float* s0 = x + (size_t)(rowBase + ar0) * C_ + k0 + ac8 * 8;
        const float* s1 = x + (size_t)(rowBase + ar0 + 32) * C_ + k0 + ac8 * 8;
        cp_async16(sb + bb + QK_XS + st0, s0);
        cp_async16(sb + bb + QK_XS + st0 + 16, s0 + 4);
        cp_async16(sb + bb + QK_XS + st1, s1);
        cp_async16(sb + bb + QK_XS + st1 + 16, s1 + 4);
    };
    // issue B-chunk c cp.asyncs into buffer base bb
    auto issueB = [&](int c, uint32_t bb) {
        const char* gh = g_wBh + c * 24576;
#pragma unroll
        for (int t = 0; t < 6; t++)
            cp_async16(sb + bb + 8192 + tid * 16 + t * 4096, gh + tid * 16 + t * 4096);
    };
    // convert staged fp32 x in buffer bb -> fp16 A tile in buffer bb
    auto cvtA = [&](uint32_t bb) {
        float4 v0a = *(const float4*)(sm + bb + QK_XS + st0);
        float4 v0b = *(const float4*)(sm + bb + QK_XS + st0 + 16);
        float4 v1a = *(const float4*)(sm + bb + QK_XS + st1);
        float4 v1b = *(const float4*)(sm + bb + QK_XS + st1 + 16);
        uint4 p0, p1;
        p0.x = h2pack(v0a.y, v0a.x);
        p0.y = h2pack(v0a.w, v0a.z);
        p0.z = h2pack(v0b.y, v0b.x);
        p0.w = h2pack(v0b.w, v0b.z);
        p1.x = h2pack(v1a.y, v1a.x);
        p1.y = h2pack(v1a.w, v1a.z);
        p1.z = h2pack(v1b.y, v1b.x);
        p1.w = h2pack(v1b.w, v1b.z);
        *(uint4*)(sm + bb + SW128((uint32_t)(ar0 * 128 + ac8 * 16))) = p0;
        *(uint4*)(sm + bb + SW128((uint32_t)((ar0 + 32) * 128 + ac8 * 16))) = p1;
    };

    // ---- prologue ----
    {
        issueB(0, 0);
        issueX(0, 0);
        asm volatile("cp.async.commit_group;" ::: "memory");   // G0: B0+X0
        issueX(1, QK_BUF);
        asm volatile("cp.async.commit_group;" ::: "memory");   // G1: X1
        asm volatile("cp.async.wait_group 1;" ::: "memory");   // G0 done
        cvtA(0);
        __syncthreads();
    }

    for (int ch = 0; ch < 16; ch++) {
        const uint32_t cb = (uint32_t)(ch & 1) * QK_BUF;
        const uint32_t nb = (uint32_t)((ch + 1) & 1) * QK_BUF;

        if (ch + 1 < 16) {
            issueB(ch + 1, nb);
            asm volatile("cp.async.commit_group;" ::: "memory");  // {B ch+1}
        }
        if (ch + 2 < 16) {
            issueX(ch + 2, cb);   // stage of cb is free (X ch already converted)
            asm volatile("cp.async.commit_group;" ::: "memory");  // {X ch+2}
        }

        // ---- MMA on buffer cb ----
#pragma unroll
        for (int s = 0; s < 4; s++) {
            const uint32_t ks16 = (uint32_t)(s * 32);
            uint32_t bh[3][4];
#pragma unroll
            for (int tn = 0; tn < 3; tn++) {
                uint32_t off = (uint32_t)((wn + tn * 16 + b_n) * 128) + ks16 + b_kb;
                ldsm_x4(bh[tn], sb + cb + 8192 + SW128(off));
            }
            uint32_t af[2][4];
#pragma unroll
            for (int tm = 0; tm < 2; tm++) {
                uint32_t off = (uint32_t)((wm + tm * 16 + a_row) * 128) + ks16 + a_kb;
                ldsm_x4(af[tm], sb + cb + SW128(off));
            }
#pragma unroll
            for (int tm = 0; tm < 2; tm++)
#pragma unroll
                for (int tn = 0; tn < 3; tn++) {
                    mma16816h(acc[tm][tn * 2 + 0], af[tm], &bh[tn][0]);
                    mma16816h(acc[tm][tn * 2 + 1], af[tm], &bh[tn][2]);
                }
        }

        if (ch + 1 < 16) {
            if (ch + 2 < 16) {
                // newest group {X ch+2} may stay in flight; everything older
                // (incl. {B ch+1} and {X ch+1}) must be complete.
                asm volatile("cp.async.wait_group 1;" ::: "memory");
            } else {
                asm volatile("cp.async.wait_group 0;" ::: "memory");
            }
            cvtA(nb);
        }
        __syncthreads();
    }

    // Epilogue: store fp16 plane
    const int er = lane >> 2;
    const int ec = (lane & 3) * 2;
#pragma unroll
    for (int tm = 0; tm < 2; tm++) {
        int r0 = rowBase + wm + tm * 16 + er;
#pragma unroll
        for (int tn = 0; tn < 6; tn++) {
            int cc = wn + tn * 8 + ec;
            *(uint32_t*)(g_h + (size_t)r0 * NW + cc) =
                h2pack(acc[tm][tn][1], acc[tm][tn][0]);
            *(uint32_t*)(g_h + (size_t)(r0 + 8) * NW + cc) =
                h2pack(acc[tm][tn][3], acc[tm][tn][2]);
        }
    }
}

// ---------------------------------------------------------------------------
// Kernel 2: banded tensor-core attention, 1-term fp16 PV (unchanged R11).
// ---------------------------------------------------------------------------
#define ATT_Q  0
#define ATT_K  8192
#define ATT_VH 32768
#define ATT_SMEM 57344
#define C1f 0.045084246f      // (1/32) * log2(e)
#define C2f 1.0201941f        // slope * log2(e)

__global__ __launch_bounds__(128) void attn_kernel(float* __restrict__ out) {
    extern __shared__ char sm[];
    const uint32_t sb = smem_u32(sm);
    const int b = blockIdx.y;
    const int q0 = blockIdx.x * 64;
    const int tid = threadIdx.x;
    const int w = tid >> 5;
    const int lane = tid & 31;

#pragma unroll
    for (int t = 0; t < 16; t++) {
        int idx = tid + t * 128;
        const __half* src;
        uint32_t dst;
        if (idx < 512) {
            int qr = idx >> 3, c = idx & 7;
            src = g_h + (size_t)(b * T_ + q0 + qr) * NW + c * 8;
            dst = sb + ATT_Q + SW128((uint32_t)(qr * 128 + c * 16));
        } else {
            int i2 = idx - 512;
            int r = i2 >> 3, c = i2 & 7;
            int j = q0 - 128 + r;
            if (j < 0) j = 0;
            src = g_h + (size_t)(b * T_ + j) * NW + 64 + c * 8;
            dst = sb + ATT_K + SW128((uint32_t)(r * 128 + c * 16));
        }
        cp_async16(dst, src);
    }
    asm volatile("cp.async.commit_group;" ::: "memory");
#pragma unroll
    for (int t = 0; t < 12; t++) {
        int idx = tid + t * 128;
        int r = idx >> 3, c = idx & 7;
        int j = q0 - 128 + r;
        if (j < 0) j = 0;
        const __half* src = g_h + (size_t)(b * T_ + j) * NW + 128 + c * 8;
        uint32_t dst = sb + ATT_VH + SW128((uint32_t)(r * 128 + c * 16));
        cp_async16(dst, src);
    }
    asm volatile("cp.async.commit_group;" ::: "memory");
    asm volatile("cp.async.wait_group 1;" ::: "memory");
    __syncthreads();

    const uint32_t a_row = (uint32_t)(lane & 15);
    const uint32_t a_kb  = (uint32_t)((lane >> 4) * 16);
    const uint32_t b_n   = (uint32_t)((lane & 7) + ((lane >> 4) << 3));
    const uint32_t b_kb  = (uint32_t)(((lane >> 3) & 1) * 16);

    uint32_t af[4][4];
#pragma unroll
    for (int s = 0; s < 4; s++)
        ldsm_x4(af[s], sb + ATT_Q +
                SW128((uint32_t)((w * 16 + a_row) * 128 + s * 32) + a_kb));

    float c[18][4];
#pragma unroll
    for (int j = 0; j < 18; j++)
#pragma unroll
        for (int k = 0; k < 4; k++) c[j][k] = 0.0f;

#pragma unroll
    for (int G = 0; G < 9; G++) {
        const int grow = (w + G) * 16;
#pragma unroll
        for (int s = 0; s < 4; s++) {
            uint32_t bk[4];
            ldsm_x4(bk, sb + ATT_K +
                    SW128((uint32_t)((grow + b_n) * 128 + s * 32) + b_kb));
            mma16816h(c[2 * G], af[s], &bk[0]);
            mma16816h(c[2 * G + 1], af[s], &bk[2]);
        }
    }

    const int g = lane >> 2;
    const int tc2 = (lane & 3) * 2;
    float rs0 = 0.0f, rs1 = 0.0f;
#pragma unroll
    for (int jt = 0; jt < 18; jt++) {
        int nb = 16 * w + 8 * jt + tc2;
        int j0 = q0 - 128 + nb;
        int d0 = g + 128 - 8 * jt - tc2;
        int d1 = d0 - 1, d2 = d0 + 8, d3 = d0 + 7;
        float p0 = ex2(fmaf(c[jt][0], C1f, -(float)d0 * C2f));
        float p1 = ex2(fmaf(c[jt][1], C1f, -(float)d1 * C2f));
        float p2 = ex2(fmaf(c[jt][2], C1f, -(float)d2 * C2f));
        float p3 = ex2(fmaf(c[jt][3], C1f, -(float)d3 * C2f));
        p0 = (d0 >= 0 && d0 < WIN && j0 >= 0) ? p0 : 0.0f;
        p1 = (d1 >= 0 && d1 < WIN && j0 + 1 >= 0) ? p1 : 0.0f;
        p2 = (d2 >= 0 && d2 < WIN && j0 >= 0) ? p2 : 0.0f;
        p3 = (d3 >= 0 && d3 < WIN && j0 + 1 >= 0) ? p3 : 0.0f;
        c[jt][0] = p0; c[jt][1] = p1; c[jt][2] = p2; c[jt][3] = p3;
        rs0 += p0 + p1;
        rs1 += p2 + p3;
    }
    rs0 += __shfl_xor_sync(0xffffffffu, rs0, 1);
    rs1 += __shfl_xor_sync(0xffffffffu, rs1, 1);
    rs0 += __shfl_xor_sync(0xffffffffu, rs0, 2);
    rs1 += __shfl_xor_sync(0xffffffffu, rs1, 2);
    const float rinv0 = 1.0f / rs0;
    const float rinv1 = 1.0f / rs1;

    asm volatile("cp.async.wait_group 0;" ::: "memory");
    __syncthreads();

    float o[8][4];
#pragma unroll
    for (int j = 0; j < 8; j++)
#pragma unroll
        for (int k = 0; k < 4; k++) o[j][k] = 0.0f;

    const uint32_t vrow = (uint32_t)((lane & 7) + 8 * ((lane >> 3) & 1));
    const uint32_t vcb  = (uint32_t)(16 * (lane >> 4));

#pragma unroll
    for (int ss = 0; ss < 9; ss++) {
        const int s = w + ss;
        uint32_t aph[4];
        aph[0] = h2pack(c[2 * ss][1], c[2 * ss][0]);
        aph[1] = h2pack(c[2 * ss][3], c[2 * ss][2]);
        aph[2] = h2pack(c[2 * ss + 1][1], c[2 * ss + 1][0]);
        aph[3] = h2pack(c[2 * ss + 1][3], c[2 * ss + 1][2]);
#pragma unroll
        for (int H = 0; H < 4; H++) {
            uint32_t ro = SW128((uint32_t)((16 * s + vrow) * 128 + 32 * H) + vcb);
            uint32_t vh[4];
            ldsm_x4t(vh, sb + ATT_VH + ro);
            mma16816h(o[2 * H], aph, &vh[0]);
            mma16816h(o[2 * H + 1], aph, &vh[2]);
        }
    }

    const int r0 = b * T_ + q0 + 16 * w + g;
#pragma unroll
    for (int j = 0; j < 8; j++) {
        *(float2*)(out + (size_t)r0 * HD + 8 * j + tc2) =
            make_float2(o[j][0] * rinv0, o[j][1] * rinv0);
        *(float2*)(out + (size_t)(r0 + 8) * HD + 8 * j + tc2) =
            make_float2(o[j][2] * rinv1, o[j][3] * rinv1);
    }
}

// ---------------------------------------------------------------------------
extern "C" void kernel_launch(void* const* d_in, const int* in_sizes, int n_in,
                              void* d_out, int out_size) {
    const float* x  = (const float*)d_in[0];
    const float* wq = (const float*)d_in[1];
    const float* wk = (const float*)d_in[2];
    const float* wv = (const float*)d_in[3];
    float* out = (float*)d_out;

    prep_w<<<96, 256>>>(wq, wk, wv);
    cudaFuncSetAttribute(qkv_mma_kernel,
                         cudaFuncAttributeMaxDynamicSharedMemorySize, QK_SMEM);
    qkv_mma_kernel<<<M_ / 64, 256, QK_SMEM>>>(x);
    cudaFuncSetAttribute(attn_kernel,
                         cudaFuncAttributeMaxDynamicSharedMemorySize, ATT_SMEM);
    attn_kernel<<<dim3(T_ / 64, B_), 128, ATT_SMEM>>>(out);
}

// round 15
// speedup vs baseline: 1.3542x; 1.1042x over previous
#include <cuda_runtime.h>
#include <cuda_fp16.h>
#include <cstdint>

// Problem constants
#define B_   4
#define T_   4096
#define C_   1024
#define HD   64
#define M_   (B_ * T_)      // 16384 rows
#define NW   192            // q(64) | k(64) | v(64) fused cols
#define WIN  128            // ALiBi window (exact to ~e^-89)

// Scratch: fused qkv fp16 [M_][192]
__device__ __align__(16) __half g_h[(size_t)M_ * NW];
__device__ __align__(16) char g_wBh[16 * 24576];  // W fp16, per-chunk SW128 images

// ---------------- smem / mma helpers ----------------
__device__ __forceinline__ uint32_t smem_u32(const void* p) {
    uint32_t a;
    asm("{ .reg .u64 t; cvta.to.shared.u64 t, %1; cvt.u32.u64 %0, t; }"
        : "=r"(a) : "l"(p));
    return a;
}
#define SW128(off) ((off) ^ (((off) >> 3) & 0x70))

__device__ __forceinline__ void ldsm_x4(uint32_t* r, uint32_t addr) {
    asm volatile("ldmatrix.sync.aligned.m8n8.x4.shared.b16 {%0,%1,%2,%3}, [%4];"
                 : "=r"(r[0]), "=r"(r[1]), "=r"(r[2]), "=r"(r[3]) : "r"(addr));
}
__device__ __forceinline__ void ldsm_x4t(uint32_t* r, uint32_t addr) {
    asm volatile("ldmatrix.sync.aligned.m8n8.x4.trans.shared.b16 {%0,%1,%2,%3}, [%4];"
                 : "=r"(r[0]), "=r"(r[1]), "=r"(r[2]), "=r"(r[3]) : "r"(addr));
}
__device__ __forceinline__ void mma16816h(float* c, const uint32_t* a,
                                          const uint32_t* b) {
    asm volatile(
        "mma.sync.aligned.m16n8k16.row.col.f32.f16.f16.f32 "
        "{%0,%1,%2,%3}, {%4,%5,%6,%7}, {%8,%9}, {%0,%1,%2,%3};"
        : "+f"(c[0]), "+f"(c[1]), "+f"(c[2]), "+f"(c[3])
        : "r"(a[0]), "r"(a[1]), "r"(a[2]), "r"(a[3]), "r"(b[0]), "r"(b[1]));
}
__device__ __forceinline__ void cp_async16(uint32_t s, const void* g) {
    asm volatile("{ .reg .u64 gp; cvta.to.global.u64 gp, %1;"
                 " cp.async.cg.shared.global [%0], [gp], 16; }"
                 :: "r"(s), "l"(g) : "memory");
}
__device__ __forceinline__ uint32_t h2pack(float hi_f, float lo_f) {
    uint32_t r;   // r[15:0] = fp16(lo_f), r[31:16] = fp16(hi_f)
    asm("cvt.rn.f16x2.f32 %0, %1, %2;" : "=r"(r) : "f"(hi_f), "f"(lo_f));
    return r;
}
__device__ __forceinline__ float ex2(float x) {
    float r;
    asm("ex2.approx.ftz.f32 %0, %1;" : "=f"(r) : "f"(x));
    return r;
}

// ---------------------------------------------------------------------------
// Prep kernel: round W to fp16, per-chunk SW128 images.
// ---------------------------------------------------------------------------
__global__ __launch_bounds__(256) void prep_w(const float* __restrict__ wq,
                                              const float* __restrict__ wk,
                                              const float* __restrict__ wv) {
    int idx = blockIdx.x * 256 + threadIdx.x;   // 0..24575
    int n = idx >> 7;
    int k = (idx & 127) * 8;
    const float* wr = (n < 64)  ? (wq + (size_t)n * C_)
                    : (n < 128) ? (wk + (size_t)(n - 64) * C_)
                                : (wv + (size_t)(n - 128) * C_);
    float4 v0 = *(const float4*)(wr + k);
    float4 v1 = *(const float4*)(wr + k + 4);
    int ch = k >> 6, koff = k & 63;
    uint4 p;
    p.x = h2pack(v0.y, v0.x);
    p.y = h2pack(v0.w, v0.z);
    p.z = h2pack(v1.y, v1.x);
    p.w = h2pack(v1.w, v1.z);
    *(uint4*)(g_wBh + ch * 24576 + SW128((uint32_t)(n * 128 + koff * 2))) = p;
}

// ---------------------------------------------------------------------------
// Kernel 1: QKV projection via mma.sync fp16 (single-term W).  [R11 base]
// BM=64, BN=192, BK=64, 256 threads, 8 warps = 2(M) x 4(N), warp tile 32x48.
// Double-buffered smem (32KB/buf): A fp16 @0 (8KB), Bh @8192 (24KB).
// New: epilogue staged through smem (400B row stride, conflict-free) and
// written with coalesced STG.128.
// ---------------------------------------------------------------------------
#define QK_BUF 32768
#define QK_SMEM (2 * QK_BUF)

__global__ __launch_bounds__(256) void qkv_mma_kernel(const float* __restrict__ x) {
    extern __shared__ char sm[];
    const uint32_t sb = smem_u32(sm);
    const int tid = threadIdx.x;
    const int wid = tid >> 5;
    const int lane = tid & 31;
    const int rowBase = blockIdx.x * 64;

    const int wm = (wid >> 2) * 32;
    const int wn = (wid & 3) * 48;

    float acc[2][6][4];
#pragma unroll
    for (int i = 0; i < 2; i++)
#pragma unroll
        for (int j = 0; j < 6; j++)
#pragma unroll
            for (int k = 0; k < 4; k++) acc[i][j][k] = 0.0f;

    const uint32_t a_row = (uint32_t)(lane & 15);
    const uint32_t a_kb  = (uint32_t)((lane >> 4) * 16);
    const uint32_t b_n   = (uint32_t)((lane & 7) + ((lane >> 4) << 3));
    const uint32_t b_kb  = (uint32_t)(((lane >> 3) & 1) * 16);

    const int ar0 = tid >> 3;
    const int ac8 = tid & 7;

    float4 av[4];

    // ---- prologue: chunk 0 ----
    {
#pragma unroll
        for (int t = 0; t < 6; t++)
            cp_async16(sb + 8192 + tid * 16 + t * 4096, g_wBh + tid * 16 + t * 4096);
        asm volatile("cp.async.commit_group;" ::: "memory");
#pragma unroll
        for (int t = 0; t < 2; t++) {
            const float* src = x + (size_t)(rowBase + ar0 + t * 32) * C_ + ac8 * 8;
            av[2 * t] = *(const float4*)src;
            av[2 * t + 1] = *(const float4*)(src + 4);
        }
#pragma unroll
        for (int t = 0; t < 2; t++) {
            uint4 p;
            p.x = h2pack(av[2 * t].y, av[2 * t].x);
            p.y = h2pack(av[2 * t].w, av[2 * t].z);
            p.z = h2pack(av[2 * t + 1].y, av[2 * t + 1].x);
            p.w = h2pack(av[2 * t + 1].w, av[2 * t + 1].z);
            uint32_t off = (uint32_t)((ar0 + t * 32) * 128 + ac8 * 16);
            *(uint4*)(sm + SW128(off)) = p;
        }
        asm volatile("cp.async.wait_group 0;" ::: "memory");
        __syncthreads();
    }

    for (int ch = 0; ch < 16; ch++) {
        const uint32_t cb = (uint32_t)(ch & 1) * QK_BUF;
        const uint32_t nb = (uint32_t)((ch + 1) & 1) * QK_BUF;
        const bool more = (ch < 15);

        if (more) {
            const char* gh = g_wBh + (ch + 1) * 24576;
#pragma unroll
            for (int t = 0; t < 6; t++)
                cp_async16(sb + nb + 8192 + tid * 16 + t * 4096, gh + tid * 16 + t * 4096);
            asm volatile("cp.async.commit_group;" ::: "memory");
            const int k0 = (ch + 1) * 64;
#pragma unroll
            for (int t = 0; t < 2; t++) {
                const float* src = x + (size_t)(rowBase + ar0 + t * 32) * C_ + k0 + ac8 * 8;
                av[2 * t] = *(const float4*)src;
                av[2 * t + 1] = *(const float4*)(src + 4);
            }
        }

#pragma unroll
        for (int s = 0; s < 4; s++) {
            const uint32_t ks16 = (uint32_t)(s * 32);
            uint32_t bh[3][4];
#pragma unroll
            for (int tn = 0; tn < 3; tn++) {
                uint32_t off = (uint32_t)((wn + tn * 16 + b_n) * 128) + ks16 + b_kb;
                ldsm_x4(bh[tn], sb + cb + 8192 + SW128(off));
            }
            uint32_t af[2][4];
#pragma unroll
            for (int tm = 0; tm < 2; tm++) {
                uint32_t off = (uint32_t)((wm + tm * 16 + a_row) * 128) + ks16 + a_kb;
                ldsm_x4(af[tm], sb + cb + SW128(off));
            }
#pragma unroll
            for (int tm = 0; tm < 2; tm++)
#pragma unroll
                for (int tn = 0; tn < 3; tn++) {
                    mma16816h(acc[tm][tn * 2 + 0], af[tm], &bh[tn][0]);
                    mma16816h(acc[tm][tn * 2 + 1], af[tm], &bh[tn][2]);
                }
        }

        if (more) {
#pragma unroll
            for (int t = 0; t < 2; t++) {
                uint4 p;
                p.x = h2pack(av[2 * t].y, av[2 * t].x);
                p.y = h2pack(av[2 * t].w, av[2 * t].z);
                p.z = h2pack(av[2 * t + 1].y, av[2 * t + 1].x);
                p.w = h2pack(av[2 * t + 1].w, av[2 * t + 1].z);
                uint32_t off = (uint32_t)((ar0 + t * 32) * 128 + ac8 * 16);
                *(uint4*)(sm + nb + SW128(off)) = p;
            }
            asm volatile("cp.async.wait_group 0;" ::: "memory");
        }
        __syncthreads();
    }

    // ---- Epilogue: stage fp16 in smem (stride 400B -> conflict-free STS),
    //      then coalesced STG.128 (24 threads cover one 384B row).
    const int er = lane >> 2;
    const int ec = (lane & 3) * 2;
#pragma unroll
    for (int tm = 0; tm < 2; tm++) {
#pragma unroll
        for (int tn = 0; tn < 6; tn++) {
            int row = wm + tm * 16 + er;
            int col = wn + tn * 8 + ec;
            *(uint32_t*)(sm + row * 400 + col * 2) =
                h2pack(acc[tm][tn][1], acc[tm][tn][0]);
            *(uint32_t*)(sm + (row + 8) * 400 + col * 2) =
                h2pack(acc[tm][tn][3], acc[tm][tn][2]);
        }
    }
    __syncthreads();
#pragma unroll
    for (int t = 0; t < 6; t++) {
        int q = tid + t * 256;           // 0..1535 = 64 rows x 24 float4
        int row = q / 24, c16 = q % 24;
        uint4 v = *(const uint4*)(sm + row * 400 + c16 * 16);
        *(uint4*)((char*)(g_h + (size_t)(rowBase + row) * NW) + c16 * 16) = v;
    }
}

// ---------------------------------------------------------------------------
// Kernel 2: banded tensor-core attention, 1-term fp16 PV (unchanged R11).
// ---------------------------------------------------------------------------
#define ATT_Q  0
#define ATT_K  8192
#define ATT_VH 32768
#define ATT_SMEM 57344
#define C1f 0.045084246f      // (1/32) * log2(e)
#define C2f 1.0201941f        // slope * log2(e)

__global__ __launch_bounds__(128) void attn_kernel(float* __restrict__ out) {
    extern __shared__ char sm[];
    const uint32_t sb = smem_u32(sm);
    const int b = blockIdx.y;
    const int q0 = blockIdx.x * 64;
    const int tid = threadIdx.x;
    const int w = tid >> 5;
    const int lane = tid & 31;

#pragma unroll
    for (int t = 0; t < 16; t++) {
        int idx = tid + t * 128;
        const __half* src;
        uint32_t dst;
        if (idx < 512) {
            int qr = idx >> 3, c = idx & 7;
            src = g_h + (size_t)(b * T_ + q0 + qr) * NW + c * 8;
            dst = sb + ATT_Q + SW128((uint32_t)(qr * 128 + c * 16));
        } else {
            int i2 = idx - 512;
            int r = i2 >> 3, c = i2 & 7;
            int j = q0 - 128 + r;
            if (j < 0) j = 0;
            src = g_h + (size_t)(b * T_ + j) * NW + 64 + c * 8;
            dst = sb + ATT_K + SW128((uint32_t)(r * 128 + c * 16));
        }
        cp_async16(dst, src);
    }
    asm volatile("cp.async.commit_group;" ::: "memory");
#pragma unroll
    for (int t = 0; t < 12; t++) {
        int idx = tid + t * 128;
        int r = idx >> 3, c = idx & 7;
        int j = q0 - 128 + r;
        if (j < 0) j = 0;
        const __half* src = g_h + (size_t)(b * T_ + j) * NW + 128 + c * 8;
        uint32_t dst = sb + ATT_VH + SW128((uint32_t)(r * 128 + c * 16));
        cp_async16(dst, src);
    }
    asm volatile("cp.async.commit_group;" ::: "memory");
    asm volatile("cp.async.wait_group 1;" ::: "memory");
    __syncthreads();

    const uint32_t a_row = (uint32_t)(lane & 15);
    const uint32_t a_kb  = (uint32_t)((lane >> 4) * 16);
    const uint32_t b_n   = (uint32_t)((lane & 7) + ((lane >> 4) << 3));
    const uint32_t b_kb  = (uint32_t)(((lane >> 3) & 1) * 16);

    uint32_t af[4][4];
#pragma unroll
    for (int s = 0; s < 4; s++)
        ldsm_x4(af[s], sb + ATT_Q +
                SW128((uint32_t)((w * 16 + a_row) * 128 + s * 32) + a_kb));

    float c[18][4];
#pragma unroll
    for (int j = 0; j < 18; j++)
#pragma unroll
        for (int k = 0; k < 4; k++) c[j][k] = 0.0f;

#pragma unroll
    for (int G = 0; G < 9; G++) {
        const int grow = (w + G) * 16;
#pragma unroll
        for (int s = 0; s < 4; s++) {
            uint32_t bk[4];
            ldsm_x4(bk, sb + ATT_K +
                    SW128((uint32_t)((grow + b_n) * 128 + s * 32) + b_kb));
            mma16816h(c[2 * G], af[s], &bk[0]);
            mma16816h(c[2 * G + 1], af[s], &bk[2]);
        }
    }

    const int g = lane >> 2;
    const int tc2 = (lane & 3) * 2;
    float rs0 = 0.0f, rs1 = 0.0f;
#pragma unroll
    for (int jt = 0; jt < 18; jt++) {
        int nb = 16 * w + 8 * jt + tc2;
        int j0 = q0 - 128 + nb;
        int d0 = g + 128 - 8 * jt - tc2;
        int d1 = d0 - 1, d2 = d0 + 8, d3 = d0 + 7;
        float p0 = ex2(fmaf(c[jt][0], C1f, -(float)d0 * C2f));
        float p1 = ex2(fmaf(c[jt][1], C1f, -(float)d1 * C2f));
        float p2 = ex2(fmaf(c[jt][2], C1f, -(float)d2 * C2f));
        float p3 = ex2(fmaf(c[jt][3], C1f, -(float)d3 * C2f));
        p0 = (d0 >= 0 && d0 < WIN && j0 >= 0) ? p0 : 0.0f;
        p1 = (d1 >= 0 && d1 < WIN && j0 + 1 >= 0) ? p1 : 0.0f;
        p2 = (d2 >= 0 && d2 < WIN && j0 >= 0) ? p2 : 0.0f;
        p3 = (d3 >= 0 && d3 < WIN && j0 + 1 >= 0) ? p3 : 0.0f;
        c[jt][0] = p0; c[jt][1] = p1; c[jt][2] = p2; c[jt][3] = p3;
        rs0 += p0 + p1;
        rs1 += p2 + p3;
    }
    rs0 += __shfl_xor_sync(0xffffffffu, rs0, 1);
    rs1 += __shfl_xor_sync(0xffffffffu, rs1, 1);
    rs0 += __shfl_xor_sync(0xffffffffu, rs0, 2);
    rs1 += __shfl_xor_sync(0xffffffffu, rs1, 2);
    const float rinv0 = 1.0f / rs0;
    const float rinv1 = 1.0f / rs1;

    asm volatile("cp.async.wait_group 0;" ::: "memory");
    __syncthreads();

    float o[8][4];
#pragma unroll
    for (int j = 0; j < 8; j++)
#pragma unroll
        for (int k = 0; k < 4; k++) o[j][k] = 0.0f;

    const uint32_t vrow = (uint32_t)((lane & 7) + 8 * ((lane >> 3) & 1));
    const uint32_t vcb  = (uint32_t)(16 * (lane >> 4));

#pragma unroll
    for (int ss = 0; ss < 9; ss++) {
        const int s = w + ss;
        uint32_t aph[4];
        aph[0] = h2pack(c[2 * ss][1], c[2 * ss][0]);
        aph[1] = h2pack(c[2 * ss][3], c[2 * ss][2]);
        aph[2] = h2pack(c[2 * ss + 1][1], c[2 * ss + 1][0]);
        aph[3] = h2pack(c[2 * ss + 1][3], c[2 * ss + 1][2]);
#pragma unroll
        for (int H = 0; H < 4; H++) {
            uint32_t ro = SW128((uint32_t)((16 * s + vrow) * 128 + 32 * H) + vcb);
            uint32_t vh[4];
            ldsm_x4t(vh, sb + ATT_VH + ro);
            mma16816h(o[2 * H], aph, &vh[0]);
            mma16816h(o[2 * H + 1], aph, &vh[2]);
        }
    }

    const int r0 = b * T_ + q0 + 16 * w + g;
#pragma unroll
    for (int j = 0; j < 8; j++) {
        *(float2*)(out + (size_t)r0 * HD + 8 * j + tc2) =
            make_float2(o[j][0] * rinv0, o[j][1] * rinv0);
        *(float2*)(out + (size_t)(r0 + 8) * HD + 8 * j + tc2) =
            make_float2(o[j][2] * rinv1, o[j][3] * rinv1);
    }
}

// ---------------------------------------------------------------------------
extern "C" void kernel_launch(void* const* d_in, const int* in_sizes, int n_in,
                              void* d_out, int out_size) {
    const float* x  = (const float*)d_in[0];
    const float* wq = (const float*)d_in[1];
    const float* wk = (const float*)d_in[2];
    const float* wv = (const float*)d_in[3];
    float* out = (float*)d_out;

    prep_w<<<96, 256>>>(wq, wk, wv);
    cudaFuncSetAttribute(qkv_mma_kernel,
                         cudaFuncAttributeMaxDynamicSharedMemorySize, QK_SMEM);
    qkv_mma_kernel<<<M_ / 64, 256, QK_SMEM>>>(x);
    cudaFuncSetAttribute(attn_kernel,
                         cudaFuncAttributeMaxDynamicSharedMemorySize, ATT_SMEM);
    attn_kernel<<<dim3(T_ / 64, B_), 128, ATT_SMEM>>>(out);
}